// round 4
// baseline (speedup 1.0000x reference)
#include <cuda_runtime.h>
#include <cuda_fp16.h>
#include <cstdint>

// ============================================================================
// Triplane + posenc + MLP(123->128->128->1), fused, sm_100 (warp-level HMMA).
// R4: warp-specialized producer/consumer, double-buffered H, named barriers.
//   warps 0-7  : consumers (MMA layers + epilogue), 4M x 2N tiling
//   warps 8-15 : producers (coords -> params/posenc -> bilinear gather)
// ============================================================================
#define CCH   32
#define PH    256
#define PW    256
#define TILE_PTS 128
#define THREADS  512
#define NGRP     256          // threads per role group
#define GRID_PERSIST 148      // 1 CTA / SM

// transposed planes: [3][256][256][32] fp32 (25.2 MB scratch)
__device__ float g_planesT[3u * 256u * 256u * 32u];

__device__ __forceinline__ uint32_t smem_u32(const void* p) {
    uint32_t a;
    asm("{ .reg .u64 t; cvta.to.shared.u64 t, %1; cvt.u32.u64 %0, t; }"
        : "=r"(a) : "l"(p));
    return a;
}

// Named barriers
#define BAR_CONS   1
#define BAR_PROD   2
#define BAR_FULL0  3   // +buf
#define BAR_EMPTY0 5   // +buf
#define BAR_SYNC(id, n)   asm volatile("bar.sync %0, %1;"   :: "r"(id), "r"(n) : "memory")
#define BAR_ARRIVE(id, n) asm volatile("bar.arrive %0, %1;" :: "r"(id), "r"(n) : "memory")

// XOR-swizzled fp16 [128 x 128] tile: row stride 256B, 16B chunks XORed by row&7.
__device__ __forceinline__ uint32_t toff(int row, int col) {
    return ((uint32_t)row << 8) + ((((uint32_t)(col >> 3) ^ (row & 7))) << 4)
         + ((uint32_t)(col & 7) << 1);
}

__device__ __forceinline__ void ldsm_x4(uint32_t& r0, uint32_t& r1,
                                        uint32_t& r2, uint32_t& r3, uint32_t addr) {
    asm volatile("ldmatrix.sync.aligned.m8n8.x4.shared.b16 {%0,%1,%2,%3}, [%4];"
                 : "=r"(r0), "=r"(r1), "=r"(r2), "=r"(r3) : "r"(addr));
}
__device__ __forceinline__ void mma16816(float* d, uint32_t a0, uint32_t a1,
                                         uint32_t a2, uint32_t a3,
                                         uint32_t b0, uint32_t b1) {
    asm volatile(
        "mma.sync.aligned.m16n8k16.row.col.f32.f16.f16.f32 "
        "{%0,%1,%2,%3}, {%4,%5,%6,%7}, {%8,%9}, {%0,%1,%2,%3};"
        : "+f"(d[0]), "+f"(d[1]), "+f"(d[2]), "+f"(d[3])
        : "r"(a0), "r"(a1), "r"(a2), "r"(a3), "r"(b0), "r"(b1));
}

// ---------------------------------------------------------------------------
// SMEM layout: 139264 B per CTA -> 1 CTA/SM (512 threads)
// ---------------------------------------------------------------------------
#define OFF_IDX  0                      // int[384]     (producer-private)
#define OFF_WXY  1536                   // float2[384]  (producer-private)
#define OFF_BW   (OFF_WXY + 3072)       // float2[128]  (b2, w3)
#define OFF_PART (OFF_BW + 1024)        // float[128]   (consumer partials)
#define OFF_H0   8192                   // fp16 [128x128] swizzled, buffer 0
#define OFF_H1   (OFF_H0 + 32768)       // buffer 1
#define OFF_W1T  (OFF_H1 + 32768)
#define OFF_W2T  (OFF_W1T + 32768)
#define SMEM_TOTAL (OFF_W2T + 32768)    // 139264

// ---------------------------------------------------------------------------
// Prep: transpose planes [C,H,W] -> [H,W,C]
// ---------------------------------------------------------------------------
__global__ void transpose_planes_kernel(const float* __restrict__ p0,
                                        const float* __restrict__ p1,
                                        const float* __restrict__ p2) {
    __shared__ float s[32][257];
    int b = blockIdx.x;          // 0..767
    int plane = b >> 8;
    int y = b & 255;
    const float* src = (plane == 0) ? p0 : ((plane == 1) ? p1 : p2);
    int x = threadIdx.x;
    #pragma unroll 4
    for (int c = 0; c < 32; ++c)
        s[c][x] = src[c * (PH * PW) + y * PW + x];
    __syncthreads();
    float* dst = g_planesT + ((size_t)plane << 21) + (size_t)y * (PW * CCH);
    for (int i = threadIdx.x; i < PW * CCH; i += 256)
        dst[i] = s[i & 31][i >> 5];
}

// One MLP layer: acc[2 m-tiles][8 n-tiles][4] += A(sA) @ B(sB)^T
__device__ __forceinline__ void do_layer(uint32_t sA, uint32_t sB, float* acc,
                                         int mrow, int ncol, int lane) {
    #pragma unroll
    for (int k = 0; k < 8; ++k) {
        uint32_t a[2][4];
        #pragma unroll
        for (int mi = 0; mi < 2; ++mi)
            ldsm_x4(a[mi][0], a[mi][1], a[mi][2], a[mi][3],
                    sA + toff(mrow + mi * 16 + (lane & 15),
                              k * 16 + ((lane >> 4) << 3)));
        #pragma unroll
        for (int jn = 0; jn < 4; ++jn) {
            uint32_t bb0, bb1, bb2, bb3;
            ldsm_x4(bb0, bb1, bb2, bb3,
                    sB + toff(ncol + jn * 16 + ((lane >> 4) << 3) + (lane & 7),
                              k * 16 + (((lane >> 3) & 1) << 3)));
            #pragma unroll
            for (int mi = 0; mi < 2; ++mi) {
                mma16816(&acc[(mi * 8 + 2 * jn) * 4],
                         a[mi][0], a[mi][1], a[mi][2], a[mi][3], bb0, bb1);
                mma16816(&acc[(mi * 8 + 2 * jn + 1) * 4],
                         a[mi][0], a[mi][1], a[mi][2], a[mi][3], bb2, bb3);
            }
        }
    }
}

// ---------------------------------------------------------------------------
// Main fused persistent kernel (warp-specialized)
// ---------------------------------------------------------------------------
__global__ void __launch_bounds__(THREADS, 1)
triplane_mlp_kernel(const float* __restrict__ coords,
                    const float* __restrict__ W1, const float* __restrict__ b1,
                    const float* __restrict__ W2, const float* __restrict__ b2,
                    const float* __restrict__ W3, const float* __restrict__ b3,
                    float* __restrict__ out, int npts) {
    extern __shared__ char smem[];
    const uint32_t sbase = smem_u32(smem);
    const int tid  = threadIdx.x;
    const int lane = tid & 31;

    int*    sIdx  = (int*)(smem + OFF_IDX);
    float2* sWxy  = (float2*)(smem + OFF_WXY);
    float2* bw    = (float2*)(smem + OFF_BW);
    float*  sPart = (float*)(smem + OFF_PART);

    // ---- Stage weights once (all 512 threads; b1 folded at col 123) ----
    for (int e = tid; e < 128 * 128; e += THREADS) {
        int row = e >> 7, col = e & 127;
        float v1 = (col < 123) ? W1[row * 123 + col]
                               : ((col == 123) ? b1[row] : 0.f);
        *(half*)(smem + OFF_W1T + toff(row, col)) = __float2half_rn(v1);
        *(half*)(smem + OFF_W2T + toff(row, col)) = __float2half_rn(W2[row * 128 + col]);
    }
    if (tid < 128)
        bw[tid] = make_float2(b2[tid], W3[tid]);
    const float b3v = b3[0];
    __syncthreads();

    const uint32_t sW1 = sbase + OFF_W1T;
    const uint32_t sW2 = sbase + OFF_W2T;
    const int ntiles = npts >> 7;
    const bool is_cons = (tid < NGRP);

    if (is_cons) {
        // ================= CONSUMER: MMA + epilogue =================
        const int wid  = tid >> 5;             // 0..7
        const int mrow = (wid >> 1) * 32;      // 4(M) x 2(N)
        const int ncol = (wid & 1) * 64;
        int iter = 0;
        for (int tile = blockIdx.x; tile < ntiles; tile += gridDim.x, ++iter) {
            const int buf = iter & 1;
            const uint32_t sH = sbase + (buf ? OFF_H1 : OFF_H0);
            char* hT = smem + (buf ? OFF_H1 : OFF_H0);

            BAR_SYNC(BAR_FULL0 + buf, THREADS);   // wait gather done

            // ---- Layer 1 ----
            float acc[64];
            #pragma unroll
            for (int j = 0; j < 64; ++j) acc[j] = 0.f;
            do_layer(sH, sW1, acc, mrow, ncol, lane);
            BAR_SYNC(BAR_CONS, NGRP);             // all consumers done reading H

            // relu -> fp16 -> A2 overwrites H[buf]
            #pragma unroll
            for (int mi = 0; mi < 2; ++mi) {
                int r0 = mrow + mi * 16 + (lane >> 2);
                #pragma unroll
                for (int j = 0; j < 8; ++j) {
                    int c = ncol + j * 8 + (lane & 3) * 2;
                    const float* a4 = &acc[(mi * 8 + j) * 4];
                    *(half2*)(hT + toff(r0, c)) =
                        __floats2half2_rn(fmaxf(a4[0], 0.f), fmaxf(a4[1], 0.f));
                    *(half2*)(hT + toff(r0 + 8, c)) =
                        __floats2half2_rn(fmaxf(a4[2], 0.f), fmaxf(a4[3], 0.f));
                }
            }
            BAR_SYNC(BAR_CONS, NGRP);

            // ---- Layer 2 ----
            #pragma unroll
            for (int j = 0; j < 64; ++j) acc[j] = 0.f;
            do_layer(sH, sW2, acc, mrow, ncol, lane);
            BAR_ARRIVE(BAR_EMPTY0 + buf, THREADS);  // release buffer to producer

            // ---- Epilogue: out = relu(D2 + b2) . W3 + b3 ----
            float part[4];
            #pragma unroll
            for (int q = 0; q < 4; ++q) part[q] = 0.f;
            #pragma unroll
            for (int mi = 0; mi < 2; ++mi) {
                #pragma unroll
                for (int j = 0; j < 8; ++j) {
                    int c = ncol + j * 8 + (lane & 3) * 2;
                    float2 bw0 = bw[c];
                    float2 bw1 = bw[c + 1];
                    const float* a4 = &acc[(mi * 8 + j) * 4];
                    part[mi * 2 + 0] += fmaxf(a4[0] + bw0.x, 0.f) * bw0.y
                                      + fmaxf(a4[1] + bw1.x, 0.f) * bw1.y;
                    part[mi * 2 + 1] += fmaxf(a4[2] + bw0.x, 0.f) * bw0.y
                                      + fmaxf(a4[3] + bw1.x, 0.f) * bw1.y;
                }
            }
            #pragma unroll
            for (int q = 0; q < 4; ++q) {
                part[q] += __shfl_xor_sync(0xFFFFFFFF, part[q], 1);
                part[q] += __shfl_xor_sync(0xFFFFFFFF, part[q], 2);
            }
            if ((wid & 1) && (lane & 3) == 0) {
                #pragma unroll
                for (int q = 0; q < 4; ++q) {
                    int row = mrow + (q >> 1) * 16 + (q & 1) * 8 + (lane >> 2);
                    sPart[row] = part[q];
                }
            }
            BAR_SYNC(BAR_CONS, NGRP);
            if (!(wid & 1) && (lane & 3) == 0) {
                size_t g = (size_t)tile * TILE_PTS;
                #pragma unroll
                for (int q = 0; q < 4; ++q) {
                    int row = mrow + (q >> 1) * 16 + (q & 1) * 8 + (lane >> 2);
                    out[g + row] = part[q] + sPart[row] + b3v;
                }
            }
            // sPart reuse next tile is guarded by the next BAR_CONS after layer 1
        }
    } else {
        // ================= PRODUCER: params + posenc + gather =================
        const int ptid = tid - NGRP;           // 0..255
        int iter = 0;
        for (int tile = blockIdx.x; tile < ntiles; tile += gridDim.x, ++iter) {
            const int buf = iter & 1;
            char* hT = smem + (buf ? OFF_H1 : OFF_H0);

            if (iter >= 2) BAR_SYNC(BAR_EMPTY0 + buf, THREADS);

            // ---- Phase A: per-point params + posenc cols 96..127 ----
            if (ptid < 128) {
                int gi = tile * TILE_PTS + ptid;
                float cx = coords[(size_t)gi * 3 + 0];
                float cy = coords[(size_t)gi * 3 + 1];
                float cz = coords[(size_t)gi * 3 + 2];
                const float uu[3] = {cx, cy, cx};
                const float vv[3] = {cy, cz, cz};
                #pragma unroll
                for (int pl = 0; pl < 3; ++pl) {
                    float fx = (uu[pl] + 1.f) * 127.5f;
                    float fy = (vv[pl] + 1.f) * 127.5f;
                    int x0 = (int)floorf(fx);
                    int y0 = (int)floorf(fy);
                    x0 = max(0, min(PW - 2, x0));
                    y0 = max(0, min(PH - 2, y0));
                    sIdx[ptid * 3 + pl] = y0 * PW + x0;
                    sWxy[ptid * 3 + pl] = make_float2(fx - (float)x0, fy - (float)y0);
                }
                const float c3[3] = {cx, cy, cz};
                #pragma unroll
                for (int j = 0; j < 3; ++j)
                    *(half*)(hT + toff(ptid, 96 + j)) = __float2half_rn(c3[j]);
                #pragma unroll
                for (int fi = 0; fi < 4; ++fi) {
                    float f = (float)(1 << fi);
                    #pragma unroll
                    for (int j = 0; j < 3; ++j) {
                        float a = c3[j] * f;
                        *(half*)(hT + toff(ptid, 99 + fi * 6 + j))  = __float2half_rn(__sinf(a));
                        *(half*)(hT + toff(ptid, 102 + fi * 6 + j)) = __float2half_rn(__cosf(a));
                    }
                }
                *(half*)(hT + toff(ptid, 123)) = __float2half_rn(1.f);   // bias col
                *(half*)(hT + toff(ptid, 124)) = __float2half_rn(0.f);
                *(half*)(hT + toff(ptid, 125)) = __float2half_rn(0.f);
                *(half*)(hT + toff(ptid, 126)) = __float2half_rn(0.f);
                *(half*)(hT + toff(ptid, 127)) = __float2half_rn(0.f);
            }
            BAR_SYNC(BAR_PROD, NGRP);

            // ---- Phase B: bilinear gather -> H cols 0..95 ----
            #pragma unroll
            for (int itb = 0; itb < 12; ++itb) {
                int i = ptid + itb * NGRP;        // 3072 items
                int p = i / 24;
                int rem = i - p * 24;
                int pl = rem >> 3;
                int ch = rem & 7;
                int pp = p * 3 + pl;
                int idx = sIdx[pp];
                float2 wxy = sWxy[pp];
                float wx1 = wxy.x, wy1 = wxy.y;
                float wx0 = 1.f - wx1, wy0 = 1.f - wy1;
                const float* base = g_planesT + ((size_t)pl << 21) + (size_t)idx * CCH + ch * 4;
                float4 c00 = *(const float4*)(base);
                float4 c01 = *(const float4*)(base + CCH);
                float4 c10 = *(const float4*)(base + PW * CCH);
                float4 c11 = *(const float4*)(base + PW * CCH + CCH);
                float w00 = wx0 * wy0, w01 = wx1 * wy0, w10 = wx0 * wy1, w11 = wx1 * wy1;
                float r0 = c00.x * w00 + c01.x * w01 + c10.x * w10 + c11.x * w11;
                float r1 = c00.y * w00 + c01.y * w01 + c10.y * w10 + c11.y * w11;
                float r2 = c00.z * w00 + c01.z * w01 + c10.z * w10 + c11.z * w11;
                float r3 = c00.w * w00 + c01.w * w01 + c10.w * w10 + c11.w * w11;
                uint32_t off = toff(p, pl * 32 + ch * 4);
                *(half2*)(hT + off)     = __floats2half2_rn(r0, r1);
                *(half2*)(hT + off + 4) = __floats2half2_rn(r2, r3);
            }
            BAR_SYNC(BAR_PROD, NGRP);             // gather done before next Phase A
            BAR_ARRIVE(BAR_FULL0 + buf, THREADS); // hand buffer to consumers
        }
    }
}

// ---------------------------------------------------------------------------
// Launch: inputs 0 coords, 1-3 planes, 4 W1, 5 b1, 6 W2, 7 b2, 8 W3, 9 b3
// ---------------------------------------------------------------------------
extern "C" void kernel_launch(void* const* d_in, const int* in_sizes, int n_in,
                              void* d_out, int out_size) {
    const float* coords = (const float*)d_in[0];
    const float* p0 = (const float*)d_in[1];
    const float* p1 = (const float*)d_in[2];
    const float* p2 = (const float*)d_in[3];
    const float* W1 = (const float*)d_in[4];
    const float* b1 = (const float*)d_in[5];
    const float* W2 = (const float*)d_in[6];
    const float* b2 = (const float*)d_in[7];
    const float* W3 = (const float*)d_in[8];
    const float* b3 = (const float*)d_in[9];
    float* out = (float*)d_out;
    int npts = out_size;

    transpose_planes_kernel<<<3 * PH, 256>>>(p0, p1, p2);

    cudaFuncSetAttribute(triplane_mlp_kernel,
                         cudaFuncAttributeMaxDynamicSharedMemorySize, SMEM_TOTAL);
    triplane_mlp_kernel<<<GRID_PERSIST, THREADS, SMEM_TOTAL>>>(
        coords, W1, b1, W2, b2, W3, b3, out, npts);
}

// round 5
// speedup vs baseline: 1.0594x; 1.0594x over previous
#include <cuda_runtime.h>
#include <cuda_fp16.h>
#include <cstdint>

// ============================================================================
// Triplane + posenc + MLP(123->128->128->1), fused, sm_100 (warp-level HMMA).
// R5: fp16 transposed planes (halved gather bytes), R3 structure
//     (2 CTAs/SM x 256 thr, 4M x 2N warp tiling), one fewer barrier.
// ============================================================================
#define CCH   32
#define PH    256
#define PW    256
#define TILE_PTS 128
#define THREADS  256
#define GRID_PERSIST 296   // 148 SMs x 2 CTAs

// transposed planes: [3][256][256][32] fp16 (12.6 MB scratch, L2-resident)
__device__ __half g_planesHT[3u * 256u * 256u * 32u];

__device__ __forceinline__ uint32_t smem_u32(const void* p) {
    uint32_t a;
    asm("{ .reg .u64 t; cvta.to.shared.u64 t, %1; cvt.u32.u64 %0, t; }"
        : "=r"(a) : "l"(p));
    return a;
}

// XOR-swizzled fp16 [128 x 128] tile: row stride 256B, 16B chunks XORed by row&7.
__device__ __forceinline__ uint32_t toff(int row, int col) {
    return ((uint32_t)row << 8) + ((((uint32_t)(col >> 3) ^ (row & 7))) << 4)
         + ((uint32_t)(col & 7) << 1);
}

__device__ __forceinline__ void ldsm_x4(uint32_t& r0, uint32_t& r1,
                                        uint32_t& r2, uint32_t& r3, uint32_t addr) {
    asm volatile("ldmatrix.sync.aligned.m8n8.x4.shared.b16 {%0,%1,%2,%3}, [%4];"
                 : "=r"(r0), "=r"(r1), "=r"(r2), "=r"(r3) : "r"(addr));
}
__device__ __forceinline__ void mma16816(float* d, uint32_t a0, uint32_t a1,
                                         uint32_t a2, uint32_t a3,
                                         uint32_t b0, uint32_t b1) {
    asm volatile(
        "mma.sync.aligned.m16n8k16.row.col.f32.f16.f16.f32 "
        "{%0,%1,%2,%3}, {%4,%5,%6,%7}, {%8,%9}, {%0,%1,%2,%3};"
        : "+f"(d[0]), "+f"(d[1]), "+f"(d[2]), "+f"(d[3])
        : "r"(a0), "r"(a1), "r"(a2), "r"(a3), "r"(b0), "r"(b1));
}

// ---------------------------------------------------------------------------
// SMEM layout (dynamic): 106496 B per CTA -> 2 CTAs/SM
// ---------------------------------------------------------------------------
#define OFF_IDX  0                      // int[384]
#define OFF_WXY  1536                   // float2[384] (wx, wy)
#define OFF_BW   (OFF_WXY + 3072)       // float2[128] (b2, w3)
#define OFF_PART (OFF_BW + 1024)        // float[128] cross-warp partials
#define OFF_H    8192                   // fp16 [128x128] swizzled; reused as A2
#define OFF_W1T  (OFF_H + 32768)
#define OFF_W2T  (OFF_W1T + 32768)
#define SMEM_TOTAL (OFF_W2T + 32768)    // 106496

// ---------------------------------------------------------------------------
// Prep: transpose planes [C,H,W] fp32 -> [H,W,C] fp16
// ---------------------------------------------------------------------------
__global__ void transpose_planes_kernel(const float* __restrict__ p0,
                                        const float* __restrict__ p1,
                                        const float* __restrict__ p2) {
    __shared__ float s[32][257];
    int b = blockIdx.x;          // 0..767
    int plane = b >> 8;
    int y = b & 255;
    const float* src = (plane == 0) ? p0 : ((plane == 1) ? p1 : p2);
    int x = threadIdx.x;
    #pragma unroll 4
    for (int c = 0; c < 32; ++c)
        s[c][x] = src[c * (PH * PW) + y * PW + x];
    __syncthreads();
    __half* dst = g_planesHT + ((size_t)plane << 21) + (size_t)y * (PW * CCH);
    for (int i = threadIdx.x; i < PW * CCH; i += 256)
        dst[i] = __float2half_rn(s[i & 31][i >> 5]);
}

// One MLP layer: acc[2 m-tiles][8 n-tiles][4] += A(sA) @ B(sB)^T
// warp covers rows [mrow, mrow+32), cols [ncol, ncol+64)
__device__ __forceinline__ void do_layer(uint32_t sA, uint32_t sB, float* acc,
                                         int mrow, int ncol, int lane) {
    #pragma unroll
    for (int k = 0; k < 8; ++k) {
        uint32_t a[2][4];
        #pragma unroll
        for (int mi = 0; mi < 2; ++mi)
            ldsm_x4(a[mi][0], a[mi][1], a[mi][2], a[mi][3],
                    sA + toff(mrow + mi * 16 + (lane & 15),
                              k * 16 + ((lane >> 4) << 3)));
        #pragma unroll
        for (int jn = 0; jn < 4; ++jn) {
            uint32_t bb0, bb1, bb2, bb3;
            ldsm_x4(bb0, bb1, bb2, bb3,
                    sB + toff(ncol + jn * 16 + ((lane >> 4) << 3) + (lane & 7),
                              k * 16 + (((lane >> 3) & 1) << 3)));
            #pragma unroll
            for (int mi = 0; mi < 2; ++mi) {
                mma16816(&acc[(mi * 8 + 2 * jn) * 4],
                         a[mi][0], a[mi][1], a[mi][2], a[mi][3], bb0, bb1);
                mma16816(&acc[(mi * 8 + 2 * jn + 1) * 4],
                         a[mi][0], a[mi][1], a[mi][2], a[mi][3], bb2, bb3);
            }
        }
    }
}

// ---------------------------------------------------------------------------
// Main fused persistent kernel
// ---------------------------------------------------------------------------
__global__ void __launch_bounds__(THREADS, 2)
triplane_mlp_kernel(const float* __restrict__ coords,
                    const float* __restrict__ W1, const float* __restrict__ b1,
                    const float* __restrict__ W2, const float* __restrict__ b2,
                    const float* __restrict__ W3, const float* __restrict__ b3,
                    float* __restrict__ out, int npts) {
    extern __shared__ char smem[];
    const uint32_t sbase = smem_u32(smem);
    const int tid  = threadIdx.x;
    const int wid  = tid >> 5;
    const int lane = tid & 31;

    int*    sIdx  = (int*)(smem + OFF_IDX);
    float2* sWxy  = (float2*)(smem + OFF_WXY);
    float2* bw    = (float2*)(smem + OFF_BW);
    float*  sPart = (float*)(smem + OFF_PART);
    char* hT  = smem + OFF_H;

    // ---- Stage weights once (fp32 -> fp16 swizzled; b1 folded at col 123) ----
    for (int e = tid; e < 128 * 128; e += THREADS) {
        int row = e >> 7, col = e & 127;
        float v1 = (col < 123) ? W1[row * 123 + col]
                               : ((col == 123) ? b1[row] : 0.f);
        *(half*)(smem + OFF_W1T + toff(row, col)) = __float2half_rn(v1);
        *(half*)(smem + OFF_W2T + toff(row, col)) = __float2half_rn(W2[row * 128 + col]);
    }
    if (tid < 128)
        bw[tid] = make_float2(b2[tid], W3[tid]);
    const float b3v = b3[0];
    __syncthreads();

    const uint32_t sH  = sbase + OFF_H;
    const uint32_t sW1 = sbase + OFF_W1T;
    const uint32_t sW2 = sbase + OFF_W2T;
    // 4(M) x 2(N) warp grid
    const int mrow = (wid >> 1) * 32;
    const int ncol = (wid & 1) * 64;
    const int ntiles = npts >> 7;

    for (int tile = blockIdx.x; tile < ntiles; tile += gridDim.x) {
        // (prior tile fully drained by the epilogue __syncthreads)

        // ---- Phase A: per-point params + posenc (cols 96..122) + const cols ----
        if (tid < 128) {
            int gi = tile * TILE_PTS + tid;
            float cx = coords[(size_t)gi * 3 + 0];
            float cy = coords[(size_t)gi * 3 + 1];
            float cz = coords[(size_t)gi * 3 + 2];
            const float uu[3] = {cx, cy, cx};
            const float vv[3] = {cy, cz, cz};
            #pragma unroll
            for (int pl = 0; pl < 3; ++pl) {
                float fx = (uu[pl] + 1.f) * 127.5f;
                float fy = (vv[pl] + 1.f) * 127.5f;
                int x0 = (int)floorf(fx);
                int y0 = (int)floorf(fy);
                x0 = max(0, min(PW - 2, x0));
                y0 = max(0, min(PH - 2, y0));
                sIdx[tid * 3 + pl] = y0 * PW + x0;
                sWxy[tid * 3 + pl] = make_float2(fx - (float)x0, fy - (float)y0);
            }
            const float c3[3] = {cx, cy, cz};
            #pragma unroll
            for (int j = 0; j < 3; ++j)
                *(half*)(hT + toff(tid, 96 + j)) = __float2half_rn(c3[j]);
            #pragma unroll
            for (int fi = 0; fi < 4; ++fi) {
                float f = (float)(1 << fi);
                #pragma unroll
                for (int j = 0; j < 3; ++j) {
                    float a = c3[j] * f;
                    *(half*)(hT + toff(tid, 99 + fi * 6 + j))  = __float2half_rn(__sinf(a));
                    *(half*)(hT + toff(tid, 102 + fi * 6 + j)) = __float2half_rn(__cosf(a));
                }
            }
            *(half*)(hT + toff(tid, 123)) = __float2half_rn(1.f);   // bias col
            *(half*)(hT + toff(tid, 124)) = __float2half_rn(0.f);
            *(half*)(hT + toff(tid, 125)) = __float2half_rn(0.f);
            *(half*)(hT + toff(tid, 126)) = __float2half_rn(0.f);
            *(half*)(hT + toff(tid, 127)) = __float2half_rn(0.f);
        }
        __syncthreads();

        // ---- Phase B: bilinear gather (fp16 planes) -> H cols 0..95 ----
        // 1536 items: point x plane x 8-channel chunk; 16B loads, 16B stores.
        #pragma unroll
        for (int itb = 0; itb < 6; ++itb) {
            int i = tid + itb * THREADS;
            int p = i / 12;
            int rem = i - p * 12;
            int pl = rem >> 2;
            int ch = rem & 3;
            int pp = p * 3 + pl;
            int idx = sIdx[pp];
            float2 wxy = sWxy[pp];
            float wx1 = wxy.x, wy1 = wxy.y;
            float wx0 = 1.f - wx1, wy0 = 1.f - wy1;
            const __half* base = g_planesHT + ((size_t)pl << 21) + (size_t)idx * CCH + ch * 8;
            uint4 u00 = *(const uint4*)(base);
            uint4 u01 = *(const uint4*)(base + CCH);
            uint4 u10 = *(const uint4*)(base + PW * CCH);
            uint4 u11 = *(const uint4*)(base + PW * CCH + CCH);
            float w00 = wx0 * wy0, w01 = wx1 * wy0, w10 = wx0 * wy1, w11 = wx1 * wy1;
            const half2* h00 = (const half2*)&u00;
            const half2* h01 = (const half2*)&u01;
            const half2* h10 = (const half2*)&u10;
            const half2* h11 = (const half2*)&u11;
            uint4 res;
            half2* hres = (half2*)&res;
            #pragma unroll
            for (int j = 0; j < 4; ++j) {
                float2 a = __half22float2(h00[j]);
                float2 b = __half22float2(h01[j]);
                float2 c = __half22float2(h10[j]);
                float2 d = __half22float2(h11[j]);
                float r0 = a.x * w00 + b.x * w01 + c.x * w10 + d.x * w11;
                float r1 = a.y * w00 + b.y * w01 + c.y * w10 + d.y * w11;
                hres[j] = __floats2half2_rn(r0, r1);
            }
            *(uint4*)(hT + toff(p, pl * 32 + ch * 8)) = res;   // 16B aligned
        }
        __syncthreads();

        // ---- Layer 1: D1[32x64 per warp] = H @ W1^T ----
        float acc[64];
        #pragma unroll
        for (int j = 0; j < 64; ++j) acc[j] = 0.f;
        do_layer(sH, sW1, acc, mrow, ncol, lane);
        __syncthreads();   // everyone done reading H before overwrite

        // relu -> fp16 -> write A2 into H buffer
        #pragma unroll
        for (int mi = 0; mi < 2; ++mi) {
            int r0 = mrow + mi * 16 + (lane >> 2);
            #pragma unroll
            for (int j = 0; j < 8; ++j) {
                int c = ncol + j * 8 + (lane & 3) * 2;
                const float* a4 = &acc[(mi * 8 + j) * 4];
                *(half2*)(hT + toff(r0, c)) =
                    __floats2half2_rn(fmaxf(a4[0], 0.f), fmaxf(a4[1], 0.f));
                *(half2*)(hT + toff(r0 + 8, c)) =
                    __floats2half2_rn(fmaxf(a4[2], 0.f), fmaxf(a4[3], 0.f));
            }
        }
        __syncthreads();

        // ---- Layer 2: D2 = A2 @ W2^T ----
        #pragma unroll
        for (int j = 0; j < 64; ++j) acc[j] = 0.f;
        do_layer(sH, sW2, acc, mrow, ncol, lane);

        // ---- Epilogue: out = relu(D2 + b2) . W3 + b3 ----
        {
            float part[4];  // [mi*2 + half]
            #pragma unroll
            for (int q = 0; q < 4; ++q) part[q] = 0.f;
            #pragma unroll
            for (int mi = 0; mi < 2; ++mi) {
                #pragma unroll
                for (int j = 0; j < 8; ++j) {
                    int c = ncol + j * 8 + (lane & 3) * 2;
                    float2 bw0 = bw[c];
                    float2 bw1 = bw[c + 1];
                    const float* a4 = &acc[(mi * 8 + j) * 4];
                    part[mi * 2 + 0] += fmaxf(a4[0] + bw0.x, 0.f) * bw0.y
                                      + fmaxf(a4[1] + bw1.x, 0.f) * bw1.y;
                    part[mi * 2 + 1] += fmaxf(a4[2] + bw0.x, 0.f) * bw0.y
                                      + fmaxf(a4[3] + bw1.x, 0.f) * bw1.y;
                }
            }
            #pragma unroll
            for (int q = 0; q < 4; ++q) {
                part[q] += __shfl_xor_sync(0xFFFFFFFF, part[q], 1);
                part[q] += __shfl_xor_sync(0xFFFFFFFF, part[q], 2);
            }
            // cross-warp combine: odd-N warp writes partials, even-N warp sums+stores
            if ((wid & 1) && (lane & 3) == 0) {
                #pragma unroll
                for (int q = 0; q < 4; ++q) {
                    int row = mrow + (q >> 1) * 16 + (q & 1) * 8 + (lane >> 2);
                    sPart[row] = part[q];
                }
            }
            __syncthreads();
            if (!(wid & 1) && (lane & 3) == 0) {
                size_t g = (size_t)tile * TILE_PTS;
                #pragma unroll
                for (int q = 0; q < 4; ++q) {
                    int row = mrow + (q >> 1) * 16 + (q & 1) * 8 + (lane >> 2);
                    out[g + row] = part[q] + sPart[row] + b3v;
                }
            }
        }
    }
}

// ---------------------------------------------------------------------------
// Launch: inputs 0 coords, 1-3 planes, 4 W1, 5 b1, 6 W2, 7 b2, 8 W3, 9 b3
// ---------------------------------------------------------------------------
extern "C" void kernel_launch(void* const* d_in, const int* in_sizes, int n_in,
                              void* d_out, int out_size) {
    const float* coords = (const float*)d_in[0];
    const float* p0 = (const float*)d_in[1];
    const float* p1 = (const float*)d_in[2];
    const float* p2 = (const float*)d_in[3];
    const float* W1 = (const float*)d_in[4];
    const float* b1 = (const float*)d_in[5];
    const float* W2 = (const float*)d_in[6];
    const float* b2 = (const float*)d_in[7];
    const float* W3 = (const float*)d_in[8];
    const float* b3 = (const float*)d_in[9];
    float* out = (float*)d_out;
    int npts = out_size;

    transpose_planes_kernel<<<3 * PH, 256>>>(p0, p1, p2);

    cudaFuncSetAttribute(triplane_mlp_kernel,
                         cudaFuncAttributeMaxDynamicSharedMemorySize, SMEM_TOTAL);
    triplane_mlp_kernel<<<GRID_PERSIST, THREADS, SMEM_TOTAL>>>(
        coords, W1, b1, W2, b2, W3, b3, out, npts);
}